// round 7
// baseline (speedup 1.0000x reference)
#include <cuda_runtime.h>
#include <cuda_bf16.h>
#include <math.h>

// Model dims
static constexpr int kT  = 1024;   // sequence length
static constexpr int kD  = 1024;   // model dim
static constexpr int kH  = 16;     // heads
static constexpr int kFF = 4096;   // ffn dim
static constexpr int kL  = 4;      // layers
static constexpr int kV  = 32000;  // vocab

// ------------------------- scratch (device globals, no allocs) --------------
__device__ float g_h   [kT * kD];
__device__ float g_h1  [kT * kD];
__device__ float g_h2  [kT * kD];
__device__ float g_hn  [kT * kD];
__device__ float g_qkv [kT * 3 * kD];
__device__ float g_attn[kT * kD];     // swa output (pre out-proj), [T, H*DH]
__device__ float g_local[kT * kD];
__device__ float g_kp  [kT * kD];
__device__ float g_vp  [kT * kD];
__device__ float g_qp  [kT * kD];
__device__ float g_beta[kT * kH];     // [T,H], post-sigmoid
__device__ float g_cum [kH * kT];     // [H,T]
__device__ float g_dout[kT * kD];     // delta output (pre out-proj) [T, H*DM]
__device__ float g_glob[kT * kD];
__device__ float g_gate[kT * kD];
__device__ float g_mixin[kT * kD];
__device__ float g_ffg [kT * kFF];
__device__ float g_ffu [kT * kFF];

// ------------------------- GEMM (large): C = A * B^T, 128x128 tile ----------
// BK=8, 256 threads, 8x8 micro-tile, register-double-buffered global loads.
// K must be a multiple of 8.
template<bool ACC>
__global__ __launch_bounds__(256, 2)
void gemm_abt128(const float* __restrict__ A, const float* __restrict__ B,
                 float* __restrict__ C, int M, int N, int K) {
    __shared__ float As[8][128];
    __shared__ float Bs[8][128];
    const int bm = blockIdx.y * 128;
    const int bn = blockIdx.x * 128;
    const int tid = threadIdx.x;            // 0..255
    const int tx = tid & 15;                // 0..15, micro col
    const int ty = tid >> 4;                // 0..15, micro row
    const int lr = tid >> 1;                // 0..127 : tile row for loads
    const int lk = (tid & 1) * 4;           // 0 or 4 : k offset for loads
    const int gm = bm + lr;
    const int gn = bn + lr;
    const bool mok = gm < M;
    const bool nok = gn < N;
    const float* arow = A + (size_t)(mok ? gm : 0) * K + lk;
    const float* brow = B + (size_t)(nok ? gn : 0) * K + lk;
    float acc[8][8] = {};
    // prologue: fetch first tile
    float4 av = make_float4(0.f, 0.f, 0.f, 0.f);
    float4 bv = make_float4(0.f, 0.f, 0.f, 0.f);
    if (mok) av = *(const float4*)(arow);
    if (nok) bv = *(const float4*)(brow);
    for (int k0 = 0; k0 < K; k0 += 8) {
        As[lk + 0][lr] = av.x; As[lk + 1][lr] = av.y;
        As[lk + 2][lr] = av.z; As[lk + 3][lr] = av.w;
        Bs[lk + 0][lr] = bv.x; Bs[lk + 1][lr] = bv.y;
        Bs[lk + 2][lr] = bv.z; Bs[lk + 3][lr] = bv.w;
        __syncthreads();
        // prefetch next tile while computing this one
        if (k0 + 8 < K) {
            if (mok) av = *(const float4*)(arow + k0 + 8);
            if (nok) bv = *(const float4*)(brow + k0 + 8);
        }
        #pragma unroll
        for (int kk = 0; kk < 8; kk++) {
            float4 a0 = *(const float4*)&As[kk][ty * 8];
            float4 a1 = *(const float4*)&As[kk][ty * 8 + 4];
            float4 b0 = *(const float4*)&Bs[kk][tx * 8];
            float4 b1 = *(const float4*)&Bs[kk][tx * 8 + 4];
            float a[8] = {a0.x, a0.y, a0.z, a0.w, a1.x, a1.y, a1.z, a1.w};
            float b[8] = {b0.x, b0.y, b0.z, b0.w, b1.x, b1.y, b1.z, b1.w};
            #pragma unroll
            for (int i = 0; i < 8; i++)
                #pragma unroll
                for (int j = 0; j < 8; j++)
                    acc[i][j] += a[i] * b[j];
        }
        __syncthreads();
    }
    #pragma unroll
    for (int i = 0; i < 8; i++) {
        int m = bm + ty * 8 + i;
        if (m >= M) continue;
        #pragma unroll
        for (int j = 0; j < 8; j++) {
            int n = bn + tx * 8 + j;
            if (n >= N) continue;
            size_t idx = (size_t)m * N + n;
            if (ACC) C[idx] += acc[i][j];
            else     C[idx]  = acc[i][j];
        }
    }
}

// ------------- GEMM (batched x4, per-z A/B/C): Cz = Az * Bz^T ---------------
// 128x128 tile, same inner loop. Square 1024 shapes only (1024 % 128 == 0),
// so no bounds checks.
__global__ __launch_bounds__(256, 2)
void gemm_abt128_b4(const float* __restrict__ A0, const float* __restrict__ A1,
                    const float* __restrict__ A2, const float* __restrict__ A3,
                    const float* __restrict__ B0, const float* __restrict__ B1,
                    const float* __restrict__ B2, const float* __restrict__ B3,
                    float* __restrict__ C0, float* __restrict__ C1,
                    float* __restrict__ C2, float* __restrict__ C3,
                    int M, int N, int K) {
    const int z = blockIdx.z;
    const float* A = (z == 0) ? A0 : (z == 1) ? A1 : (z == 2) ? A2 : A3;
    const float* B = (z == 0) ? B0 : (z == 1) ? B1 : (z == 2) ? B2 : B3;
    float*       C = (z == 0) ? C0 : (z == 1) ? C1 : (z == 2) ? C2 : C3;
    __shared__ float As[8][128];
    __shared__ float Bs[8][128];
    const int bm = blockIdx.y * 128;
    const int bn = blockIdx.x * 128;
    const int tid = threadIdx.x;
    const int tx = tid & 15;
    const int ty = tid >> 4;
    const int lr = tid >> 1;
    const int lk = (tid & 1) * 4;
    const float* arow = A + (size_t)(bm + lr) * K + lk;
    const float* brow = B + (size_t)(bn + lr) * K + lk;
    float acc[8][8] = {};
    float4 av = *(const float4*)(arow);
    float4 bv = *(const float4*)(brow);
    for (int k0 = 0; k0 < K; k0 += 8) {
        As[lk + 0][lr] = av.x; As[lk + 1][lr] = av.y;
        As[lk + 2][lr] = av.z; As[lk + 3][lr] = av.w;
        Bs[lk + 0][lr] = bv.x; Bs[lk + 1][lr] = bv.y;
        Bs[lk + 2][lr] = bv.z; Bs[lk + 3][lr] = bv.w;
        __syncthreads();
        if (k0 + 8 < K) {
            av = *(const float4*)(arow + k0 + 8);
            bv = *(const float4*)(brow + k0 + 8);
        }
        #pragma unroll
        for (int kk = 0; kk < 8; kk++) {
            float4 a0 = *(const float4*)&As[kk][ty * 8];
            float4 a1 = *(const float4*)&As[kk][ty * 8 + 4];
            float4 b0 = *(const float4*)&Bs[kk][tx * 8];
            float4 b1 = *(const float4*)&Bs[kk][tx * 8 + 4];
            float a[8] = {a0.x, a0.y, a0.z, a0.w, a1.x, a1.y, a1.z, a1.w};
            float b[8] = {b0.x, b0.y, b0.z, b0.w, b1.x, b1.y, b1.z, b1.w};
            #pragma unroll
            for (int i = 0; i < 8; i++)
                #pragma unroll
                for (int j = 0; j < 8; j++)
                    acc[i][j] += a[i] * b[j];
        }
        __syncthreads();
    }
    #pragma unroll
    for (int i = 0; i < 8; i++) {
        int m = bm + ty * 8 + i;
        #pragma unroll
        for (int j = 0; j < 8; j++) {
            int n = bn + tx * 8 + j;
            C[(size_t)m * N + n] = acc[i][j];
        }
    }
}

// ------------- GEMM (batched x2, shared A): Cz = A * Bz^T -------------------
// For the FFN wg/wu pair: M=1024, N=4096, K=1024, multiples of 128.
__global__ __launch_bounds__(256, 2)
void gemm_abt128_b2(const float* __restrict__ A,
                    const float* __restrict__ B0, const float* __restrict__ B1,
                    float* __restrict__ C0, float* __restrict__ C1,
                    int M, int N, int K) {
    const float* B = (blockIdx.z == 0) ? B0 : B1;
    float*       C = (blockIdx.z == 0) ? C0 : C1;
    __shared__ float As[8][128];
    __shared__ float Bs[8][128];
    const int bm = blockIdx.y * 128;
    const int bn = blockIdx.x * 128;
    const int tid = threadIdx.x;
    const int tx = tid & 15;
    const int ty = tid >> 4;
    const int lr = tid >> 1;
    const int lk = (tid & 1) * 4;
    const float* arow = A + (size_t)(bm + lr) * K + lk;
    const float* brow = B + (size_t)(bn + lr) * K + lk;
    float acc[8][8] = {};
    float4 av = *(const float4*)(arow);
    float4 bv = *(const float4*)(brow);
    for (int k0 = 0; k0 < K; k0 += 8) {
        As[lk + 0][lr] = av.x; As[lk + 1][lr] = av.y;
        As[lk + 2][lr] = av.z; As[lk + 3][lr] = av.w;
        Bs[lk + 0][lr] = bv.x; Bs[lk + 1][lr] = bv.y;
        Bs[lk + 2][lr] = bv.z; Bs[lk + 3][lr] = bv.w;
        __syncthreads();
        if (k0 + 8 < K) {
            av = *(const float4*)(arow + k0 + 8);
            bv = *(const float4*)(brow + k0 + 8);
        }
        #pragma unroll
        for (int kk = 0; kk < 8; kk++) {
            float4 a0 = *(const float4*)&As[kk][ty * 8];
            float4 a1 = *(const float4*)&As[kk][ty * 8 + 4];
            float4 b0 = *(const float4*)&Bs[kk][tx * 8];
            float4 b1 = *(const float4*)&Bs[kk][tx * 8 + 4];
            float a[8] = {a0.x, a0.y, a0.z, a0.w, a1.x, a1.y, a1.z, a1.w};
            float b[8] = {b0.x, b0.y, b0.z, b0.w, b1.x, b1.y, b1.z, b1.w};
            #pragma unroll
            for (int i = 0; i < 8; i++)
                #pragma unroll
                for (int j = 0; j < 8; j++)
                    acc[i][j] += a[i] * b[j];
        }
        __syncthreads();
    }
    #pragma unroll
    for (int i = 0; i < 8; i++) {
        int m = bm + ty * 8 + i;
        #pragma unroll
        for (int j = 0; j < 8; j++) {
            int n = bn + tx * 8 + j;
            C[(size_t)m * N + n] = acc[i][j];
        }
    }
}

// ------------------------- GEMM (small): C = A * B^T, 64x64 tile ------------
// BK=16, 256 threads, 4x4 micro-tile, register-double-buffered global loads.
// K must be a multiple of 16.
template<bool ACC>
__global__ __launch_bounds__(256)
void gemm_abt64(const float* __restrict__ A, const float* __restrict__ B,
                float* __restrict__ C, int M, int N, int K) {
    __shared__ float As[16][64];
    __shared__ float Bs[16][64];
    const int bm = blockIdx.y * 64;
    const int bn = blockIdx.x * 64;
    const int tid = threadIdx.x;            // 0..255
    const int tx = tid & 15;                // col group for compute
    const int ty = tid >> 4;                // row group for compute
    const int lr = tid >> 2;                // 0..63 : tile row for loads
    const int lk = (tid & 3) * 4;           // 0,4,8,12 : k offset for loads
    const int gm = bm + lr;
    const int gn = bn + lr;
    const bool mok = gm < M;
    const bool nok = gn < N;
    const float* arow = A + (size_t)(mok ? gm : 0) * K + lk;
    const float* brow = B + (size_t)(nok ? gn : 0) * K + lk;
    float acc[4][4] = {};
    float4 av = make_float4(0.f, 0.f, 0.f, 0.f);
    float4 bv = make_float4(0.f, 0.f, 0.f, 0.f);
    if (mok) av = *(const float4*)(arow);
    if (nok) bv = *(const float4*)(brow);
    for (int k0 = 0; k0 < K; k0 += 16) {
        As[lk + 0][lr] = av.x; As[lk + 1][lr] = av.y;
        As[lk + 2][lr] = av.z; As[lk + 3][lr] = av.w;
        Bs[lk + 0][lr] = bv.x; Bs[lk + 1][lr] = bv.y;
        Bs[lk + 2][lr] = bv.z; Bs[lk + 3][lr] = bv.w;
        __syncthreads();
        if (k0 + 16 < K) {
            if (mok) av = *(const float4*)(arow + k0 + 16);
            if (nok) bv = *(const float4*)(brow + k0 + 16);
        }
        #pragma unroll
        for (int kk = 0; kk < 16; kk++) {
            float a[4], b[4];
            #pragma unroll
            for (int i = 0; i < 4; i++) a[i] = As[kk][ty * 4 + i];
            #pragma unroll
            for (int j = 0; j < 4; j++) b[j] = Bs[kk][tx * 4 + j];
            #pragma unroll
            for (int i = 0; i < 4; i++)
                #pragma unroll
                for (int j = 0; j < 4; j++)
                    acc[i][j] += a[i] * b[j];
        }
        __syncthreads();
    }
    #pragma unroll
    for (int i = 0; i < 4; i++) {
        int m = bm + ty * 4 + i;
        if (m >= M) continue;
        #pragma unroll
        for (int j = 0; j < 4; j++) {
            int n = bn + tx * 4 + j;
            if (n >= N) continue;
            size_t idx = (size_t)m * N + n;
            if (ACC) C[idx] += acc[i][j];
            else     C[idx]  = acc[i][j];
        }
    }
}

// Dispatch: 128-tile when its grid fills the chip, else 64-tile.
template<bool ACC>
static void gemm(const float* A, const float* B, float* C, int M, int N, int K) {
    int ctas128 = ((N + 127) / 128) * ((M + 127) / 128);
    if (ctas128 >= 148) {
        dim3 g((N + 127) / 128, (M + 127) / 128);
        gemm_abt128<ACC><<<g, 256>>>(A, B, C, M, N, K);
    } else {
        dim3 g((N + 63) / 64, (M + 63) / 64);
        gemm_abt64<ACC><<<g, 256>>>(A, B, C, M, N, K);
    }
}

// ------------------------- rmsnorm ------------------------------------------
__global__ void rmsnorm_k(const float* __restrict__ x, const float* __restrict__ w,
                          float* __restrict__ y) {
    int t = blockIdx.x;
    const float* xr = x + (size_t)t * kD;
    __shared__ float red[256];
    float s = 0.f;
    for (int d = threadIdx.x; d < kD; d += 256) { float v = xr[d]; s += v * v; }
    red[threadIdx.x] = s; __syncthreads();
    for (int o = 128; o > 0; o >>= 1) {
        if (threadIdx.x < o) red[threadIdx.x] += red[threadIdx.x + o];
        __syncthreads();
    }
    float scale = rsqrtf(red[0] / kD + 1e-6f);
    for (int d = threadIdx.x; d < kD; d += 256)
        y[(size_t)t * kD + d] = xr[d] * scale * w[d];
}

__global__ void embed_norm_k(const int* __restrict__ x, const float* __restrict__ embed,
                             const float* __restrict__ w, float* __restrict__ y) {
    int t = blockIdx.x;
    const float* xr = embed + (size_t)x[t] * kD;
    __shared__ float red[256];
    float s = 0.f;
    for (int d = threadIdx.x; d < kD; d += 256) { float v = xr[d]; s += v * v; }
    red[threadIdx.x] = s; __syncthreads();
    for (int o = 128; o > 0; o >>= 1) {
        if (threadIdx.x < o) red[threadIdx.x] += red[threadIdx.x + o];
        __syncthreads();
    }
    float scale = rsqrtf(red[0] / kD + 1e-6f);
    for (int d = threadIdx.x; d < kD; d += 256)
        y[(size_t)t * kD + d] = xr[d] * scale * w[d];
}

// ------------------------- sliding-window attention -------------------------
// grid (T, H), 256 threads. qkv layout [T, 3*D]: q at +0, k at +1024, v at +2048.
__global__ void swa_k(const float* __restrict__ qkv, float* __restrict__ out) {
    int i = blockIdx.x, h = blockIdx.y;
    int tid = threadIdx.x;
    __shared__ float qv[64];
    __shared__ float sp[256];
    __shared__ float red[256];
    if (tid < 64) qv[tid] = qkv[(size_t)i * 3072 + h * 64 + tid];
    __syncthreads();
    int j = i - 255 + tid;            // window: [i-255, i]
    float s;
    if (j >= 0) {
        const float* kr = qkv + (size_t)j * 3072 + 1024 + h * 64;
        float d = 0.f;
        #pragma unroll
        for (int c = 0; c < 64; c++) d += qv[c] * kr[c];
        s = d * 0.125f;
    } else {
        s = -INFINITY;
    }
    red[tid] = s; __syncthreads();
    for (int o = 128; o > 0; o >>= 1) {
        if (tid < o) red[tid] = fmaxf(red[tid], red[tid + o]);
        __syncthreads();
    }
    float m = red[0]; __syncthreads();
    float p = expf(s - m);            // -inf -> 0
    sp[tid] = p;
    red[tid] = p; __syncthreads();
    for (int o = 128; o > 0; o >>= 1) {
        if (tid < o) red[tid] += red[tid + o];
        __syncthreads();
    }
    float inv = 1.f / red[0];
    __syncthreads();
    int dh = tid & 63, part = tid >> 6;
    float acc = 0.f;
    for (int jj = part * 64; jj < part * 64 + 64; jj++) {
        int jg = i - 255 + jj;
        int jc = jg < 0 ? 0 : jg;     // sp[jj]==0 when jg<0, so clamp is safe
        acc += sp[jj] * qkv[(size_t)jc * 3072 + 2048 + h * 64 + dh];
    }
    red[tid] = acc; __syncthreads();
    if (tid < 64) {
        float o = (red[tid] + red[tid + 64] + red[tid + 128] + red[tid + 192]) * inv;
        out[(size_t)i * kD + h * 64 + tid] = o;
    }
}

// ------------------------- delta helpers ------------------------------------
__global__ void l2norm_k(float* __restrict__ p) {   // grid (T,H), 32 threads
    int t = blockIdx.x, h = blockIdx.y;
    float* r = p + (size_t)t * kD + h * 64;
    int lane = threadIdx.x;
    float v0 = r[lane], v1 = r[lane + 32];
    float s = v0 * v0 + v1 * v1;
    #pragma unroll
    for (int o = 16; o > 0; o >>= 1) s += __shfl_xor_sync(0xffffffffu, s, o);
    float n = fmaxf(sqrtf(s), 1e-12f);
    r[lane] = v0 / n; r[lane + 32] = v1 / n;
}

__global__ void sigmoid_k(float* __restrict__ p, int n) {
    int i = blockIdx.x * blockDim.x + threadIdx.x;
    if (i < n) p[i] = 1.f / (1.f + expf(-p[i]));
}

__global__ void cum_k(const float* __restrict__ beta, float* __restrict__ cum) {
    int h = threadIdx.x;  // 16 threads
    float c = 0.f;
    for (int t = 0; t < kT; t++) {
        c += logf(1.f - beta[(size_t)t * kH + h] + 1e-8f);
        cum[(size_t)h * kT + t] = c;
    }
}

// delta rule: out[i,h,:] = sum_{j>=i} (q_i.k_j/8)*exp(min(cum_i-cum_j,0))*v_j + beta*v_i
// grid (T, H), 256 threads.
__global__ void delta_k(const float* __restrict__ kp, const float* __restrict__ vp,
                        const float* __restrict__ qp, const float* __restrict__ beta,
                        const float* __restrict__ cum, float* __restrict__ out) {
    int i = blockIdx.x, h = blockIdx.y;
    int tid = threadIdx.x;
    __shared__ float qv[64];
    __shared__ float sw[256];
    __shared__ float red[256];
    if (tid < 64) qv[tid] = qp[(size_t)i * kD + h * 64 + tid];
    __syncthreads();
    float ci = cum[(size_t)h * kT + i];
    int dh = tid & 63, part = tid >> 6;
    float acc = 0.f;
    for (int jb = (i >> 8) << 8; jb < kT; jb += 256) {
        int j = jb + tid;
        float w = 0.f;
        if (j >= i) {
            const float* kr = kp + (size_t)j * kD + h * 64;
            float d = 0.f;
            #pragma unroll
            for (int c = 0; c < 64; c++) d += qv[c] * kr[c];
            float ld = ci - cum[(size_t)h * kT + j];
            w = d * 0.125f * expf(fminf(ld, 0.f));
        }
        sw[tid] = w; __syncthreads();
        for (int jj = part * 64; jj < part * 64 + 64; jj++)
            acc += sw[jj] * vp[(size_t)(jb + jj) * kD + h * 64 + dh];
        __syncthreads();
    }
    red[tid] = acc; __syncthreads();
    if (tid < 64) {
        float b = beta[(size_t)i * kH + h];
        float o = red[tid] + red[tid + 64] + red[tid + 128] + red[tid + 192]
                + b * vp[(size_t)i * kD + h * 64 + tid];
        out[(size_t)i * kD + h * 64 + tid] = o;
    }
}

// ------------------------- elementwise --------------------------------------
__global__ void mix_k(const float* __restrict__ gate, const float* __restrict__ local,
                      const float* __restrict__ glob, float* __restrict__ out, int n) {
    int i = blockIdx.x * blockDim.x + threadIdx.x;
    if (i < n) {
        float g = 1.f / (1.f + expf(-gate[i]));
        out[i] = g * local[i] + (1.f - g) * glob[i];
    }
}

__global__ void silu_mul_k(float* __restrict__ g, const float* __restrict__ u, int n) {
    int i = blockIdx.x * blockDim.x + threadIdx.x;
    if (i < n) {
        float x = g[i];
        g[i] = (x / (1.f + expf(-x))) * u[i];
    }
}

// ------------------------- host orchestration -------------------------------
static inline float* sym(const void* symbol) {
    void* p = nullptr;
    cudaGetSymbolAddress(&p, symbol);
    return (float*)p;
}

extern "C" void kernel_launch(void* const* d_in, const int* in_sizes, int n_in,
                              void* d_out, int out_size) {
    const int*   x        = (const int*)  d_in[0];
    const float* embed    = (const float*)d_in[1];
    const float* ln_in_w  = (const float*)d_in[2];
    const float* ln1_w    = (const float*)d_in[3];
    const float* lnd_w    = (const float*)d_in[4];
    const float* qkv_w    = (const float*)d_in[5];
    const float* swa_out_w= (const float*)d_in[6];
    const float* k_w      = (const float*)d_in[7];
    const float* v_w      = (const float*)d_in[8];
    const float* q_w      = (const float*)d_in[9];
    const float* beta_w   = (const float*)d_in[10];
    const float* mem_out_w= (const float*)d_in[11];
    const float* gate_w   = (const float*)d_in[12];
    const float* comb_w   = (const float*)d_in[13];
    const float* ln2_w    = (const float*)d_in[14];
    const float* wg       = (const float*)d_in[15];
    const float* wu       = (const float*)d_in[16];
    const float* wo       = (const float*)d_in[17];
    const float* ln_out_w = (const float*)d_in[18];
    float* logits = (float*)d_out;

    float* h     = sym(g_h);
    float* h1    = sym(g_h1);
    float* h2    = sym(g_h2);
    float* hn    = sym(g_hn);
    float* qkv   = sym(g_qkv);
    float* attn  = sym(g_attn);
    float* local = sym(g_local);
    float* kp    = sym(g_kp);
    float* vp    = sym(g_vp);
    float* qp    = sym(g_qp);
    float* beta  = sym(g_beta);
    float* cum   = sym(g_cum);
    float* dout  = sym(g_dout);
    float* glob  = sym(g_glob);
    float* gate  = sym(g_gate);
    float* mixin = sym(g_mixin);
    float* ffg   = sym(g_ffg);
    float* ffu   = sym(g_ffu);

    // h = rms_norm(embed[x], ln_in_w)
    embed_norm_k<<<kT, 256>>>(x, embed, ln_in_w, h);

    for (int l = 0; l < kL; l++) {
        const float* qkv_wl  = qkv_w    + (size_t)l * 3 * kD * kD;
        const float* swo_wl  = swa_out_w+ (size_t)l * kD * kD;
        const float* k_wl    = k_w      + (size_t)l * kD * kD;
        const float* v_wl    = v_w      + (size_t)l * kD * kD;
        const float* q_wl    = q_w      + (size_t)l * kD * kD;
        const float* beta_wl = beta_w   + (size_t)l * kH * kD;
        const float* mo_wl   = mem_out_w+ (size_t)l * kD * kD;
        const float* gate_wl = gate_w   + (size_t)l * kD * kD;
        const float* comb_wl = comb_w   + (size_t)l * kD * kD;
        const float* wg_l    = wg       + (size_t)l * kFF * kD;
        const float* wu_l    = wu       + (size_t)l * kFF * kD;
        const float* wo_l    = wo       + (size_t)l * kD * kFF;

        rmsnorm_k<<<kT, 256>>>(h, ln1_w + (size_t)l * kD, h1);
        rmsnorm_k<<<kT, 256>>>(h, lnd_w + (size_t)l * kD, h2);

        // local branch: qkv projection + attention
        gemm<false>(h1, qkv_wl, qkv, kT, 3 * kD, kD);
        swa_k<<<dim3(kT, kH), 256>>>(qkv, attn);
        gemm<false>(attn, swo_wl, local, kT, kD, kD);

        // batched: gate (h1) + k/v/q projections (h2) — 4 x 64 = 256 CTAs
        {
            dim3 g(kD / 128, kT / 128, 4);
            gemm_abt128_b4<<<g, 256>>>(h1, h2, h2, h2,
                                       gate_wl, k_wl, v_wl, q_wl,
                                       gate, kp, vp, qp, kT, kD, kD);
        }
        gemm<false>(h2, beta_wl, beta, kT, kH, kD);
        sigmoid_k<<<(kT * kH + 255) / 256, 256>>>(beta, kT * kH);
        l2norm_k<<<dim3(kT, kH), 32>>>(kp);
        l2norm_k<<<dim3(kT, kH), 32>>>(qp);
        cum_k<<<1, kH>>>(beta, cum);
        delta_k<<<dim3(kT, kH), 256>>>(kp, vp, qp, beta, cum, dout);
        gemm<false>(dout, mo_wl, glob, kT, kD, kD);

        // gate mix + combine, residual
        mix_k<<<(kT * kD + 255) / 256, 256>>>(gate, local, glob, mixin, kT * kD);
        gemm<true>(mixin, comb_wl, h, kT, kD, kD);

        // FFN, residual (wg/wu batched, shared A = hn)
        rmsnorm_k<<<kT, 256>>>(h, ln2_w + (size_t)l * kD, hn);
        {
            dim3 g(kFF / 128, kT / 128, 2);  // 32 x 8 x 2 = 512 CTAs
            gemm_abt128_b2<<<g, 256>>>(hn, wg_l, wu_l, ffg, ffu, kT, kFF, kD);
        }
        silu_mul_k<<<(kT * kFF + 255) / 256, 256>>>(ffg, ffu, kT * kFF);
        gemm<true>(ffg, wo_l, h, kT, kD, kFF);
    }

    // logits = rms_norm(h, ln_out_w) @ embed^T
    rmsnorm_k<<<kT, 256>>>(h, ln_out_w, hn);
    gemm<false>(hn, embed, logits, kT, kV, kD);
}

// round 17
// speedup vs baseline: 1.0226x; 1.0226x over previous
#include <cuda_runtime.h>
#include <cuda_bf16.h>
#include <math.h>
#include <stdint.h>

// Model dims
static constexpr int kT  = 1024;   // sequence length
static constexpr int kD  = 1024;   // model dim
static constexpr int kH  = 16;     // heads
static constexpr int kFF = 4096;   // ffn dim
static constexpr int kL  = 4;      // layers
static constexpr int kV  = 32000;  // vocab

// ------------------------- scratch (device globals, no allocs) --------------
__device__ float g_h   [kT * kD];
__device__ float g_h1  [kT * kD];
__device__ float g_h2  [kT * kD];
__device__ float g_hn  [kT * kD];
__device__ float g_qkv [kT * 3 * kD];
__device__ float g_attn[kT * kD];
__device__ float g_local[kT * kD];
__device__ float g_kp  [kT * kD];
__device__ float g_vp  [kT * kD];
__device__ float g_qp  [kT * kD];
__device__ float g_beta[kT * kH];
__device__ float g_cum [kH * kT];
__device__ float g_dout[kT * kD];
__device__ float g_glob[kT * kD];
__device__ float g_gate[kT * kD];
__device__ float g_mixin[kT * kD];
__device__ float g_ffg [kT * kFF];
__device__ float g_ffu [kT * kFF];

// ------------------------- tf32 helpers -------------------------------------
__device__ __forceinline__ uint32_t f2tf32(float a) {
    uint32_t r;
    asm("cvt.rna.tf32.f32 %0, %1;" : "=r"(r) : "f"(a));
    return r;
}
__device__ __forceinline__ void split_tf32(float a, uint32_t& hi, uint32_t& lo) {
    hi = f2tf32(a);
    lo = f2tf32(a - __uint_as_float(hi));
}
__device__ __forceinline__ void mma_tf32(float* c, const uint32_t* a, const uint32_t* b) {
    asm volatile("mma.sync.aligned.m16n8k8.row.col.f32.tf32.tf32.f32 "
        "{%0,%1,%2,%3}, {%4,%5,%6,%7}, {%8,%9}, {%0,%1,%2,%3};"
        : "+f"(c[0]), "+f"(c[1]), "+f"(c[2]), "+f"(c[3])
        : "r"(a[0]), "r"(a[1]), "r"(a[2]), "r"(a[3]), "r"(b[0]), "r"(b[1]));
}
__device__ __forceinline__ void cp16(uint32_t saddr, const float* g) {
    asm volatile("cp.async.ca.shared.global [%0], [%1], 16;" :: "r"(saddr), "l"(g));
}

// ------------------------- tf32 GEMM: C[M,N] = A[M,K] * B[N,K]^T -------------
// 3xTF32 (hi/lo split) for ~fp32 accuracy on tensor cores.
// 128x128 tile, BK=16, 256 threads (8 warps as 2x4), 64x32 per warp.
// Requires: M % 128 == 0, N % 128 == 0, K % 16 == 0. (All shapes here qualify
// except the beta GEMM which uses the FFMA fallback.)
static constexpr int PAD = 20;   // floats per smem row (16 data + 4 pad)

template<bool ACC>
__device__ __forceinline__ void gemm_tf32_dev(
    const float* __restrict__ A, const float* __restrict__ B,
    float* __restrict__ C, int M, int N, int K) {
    __shared__ __align__(16) float As[2][128][PAD];
    __shared__ __align__(16) float Bs[2][128][PAD];
    const int tid = threadIdx.x;
    const int wid = tid >> 5, lane = tid & 31;
    const int wm = wid >> 2;          // 0..1
    const int wn = wid & 3;           // 0..3
    const int bm = blockIdx.y * 128;
    const int bn = blockIdx.x * 128;
    const int r = lane >> 2;          // 0..7
    const int c = lane & 3;           // 0..3
    // loader mapping: 2 threads per row, each loads 8 consecutive k (2x float4)
    const int lrow = tid >> 1;        // 0..127
    const int lk   = (tid & 1) * 8;   // 0 or 8
    const float* ag = A + (size_t)(bm + lrow) * K + lk;
    const float* bg = B + (size_t)(bn + lrow) * K + lk;
    const uint32_t sa = (uint32_t)__cvta_generic_to_shared(&As[0][lrow][lk]);
    const uint32_t sb = (uint32_t)__cvta_generic_to_shared(&Bs[0][lrow][lk]);
    const uint32_t bufstride = 128 * PAD * 4;

    float acc[4][4][4] = {};

    // prologue: issue first tile
    cp16(sa, ag); cp16(sa + 16, ag + 4);
    cp16(sb, bg); cp16(sb + 16, bg + 4);
    asm volatile("cp.async.commit_group;");

    int buf = 0;
    for (int k0 = 0; k0 < K; k0 += 16) {
        const bool more = (k0 + 16 < K);
        __syncthreads();               // prior compute on buf^1 fully done
        if (more) {
            uint32_t da = sa + (buf ^ 1) * bufstride;
            uint32_t db = sb + (buf ^ 1) * bufstride;
            cp16(da, ag + k0 + 16); cp16(da + 16, ag + k0 + 20);
            cp16(db, bg + k0 + 16); cp16(db + 16, bg + k0 + 20);
            asm volatile("cp.async.commit_group;");
            asm volatile("cp.async.wait_group 1;");
        } else {
            asm volatile("cp.async.wait_group 0;");
        }
        __syncthreads();               // loaded data visible

        #pragma unroll
        for (int ks = 0; ks < 16; ks += 8) {
            uint32_t ah[4][4], al[4][4];
            #pragma unroll
            for (int mt = 0; mt < 4; mt++) {
                int mrow = wm * 64 + mt * 16 + r;
                split_tf32(As[buf][mrow    ][ks + c    ], ah[mt][0], al[mt][0]);
                split_tf32(As[buf][mrow + 8][ks + c    ], ah[mt][1], al[mt][1]);
                split_tf32(As[buf][mrow    ][ks + c + 4], ah[mt][2], al[mt][2]);
                split_tf32(As[buf][mrow + 8][ks + c + 4], ah[mt][3], al[mt][3]);
            }
            #pragma unroll
            for (int nt = 0; nt < 4; nt++) {
                int ncol = wn * 32 + nt * 8 + r;
                uint32_t bh[2], bl[2];
                split_tf32(Bs[buf][ncol][ks + c    ], bh[0], bl[0]);
                split_tf32(Bs[buf][ncol][ks + c + 4], bh[1], bl[1]);
                #pragma unroll
                for (int mt = 0; mt < 4; mt++) {
                    mma_tf32(acc[mt][nt], ah[mt], bh);   // Ah*Bh
                    mma_tf32(acc[mt][nt], al[mt], bh);   // Al*Bh
                    mma_tf32(acc[mt][nt], ah[mt], bl);   // Ah*Bl
                }
            }
        }
        buf ^= 1;
    }

    // epilogue
    #pragma unroll
    for (int mt = 0; mt < 4; mt++) {
        int row0 = bm + wm * 64 + mt * 16 + r;
        #pragma unroll
        for (int nt = 0; nt < 4; nt++) {
            int col = bn + wn * 32 + nt * 8 + 2 * c;
            float* p0 = C + (size_t)row0 * N + col;
            float* p1 = C + (size_t)(row0 + 8) * N + col;
            if (ACC) {
                p0[0] += acc[mt][nt][0]; p0[1] += acc[mt][nt][1];
                p1[0] += acc[mt][nt][2]; p1[1] += acc[mt][nt][3];
            } else {
                p0[0] = acc[mt][nt][0]; p0[1] = acc[mt][nt][1];
                p1[0] = acc[mt][nt][2]; p1[1] = acc[mt][nt][3];
            }
        }
    }
}

__global__ __launch_bounds__(256, 2)
void gemm_tf32_k(const float* __restrict__ A, const float* __restrict__ B,
                 float* __restrict__ C, int M, int N, int K) {
    gemm_tf32_dev<false>(A, B, C, M, N, K);
}
__global__ __launch_bounds__(256, 2)
void gemm_tf32_acc_k(const float* __restrict__ A, const float* __restrict__ B,
                     float* __restrict__ C, int M, int N, int K) {
    gemm_tf32_dev<true>(A, B, C, M, N, K);
}
// batched x4, per-z A/B/C (gate + k/v/q projections)
__global__ __launch_bounds__(256, 2)
void gemm_tf32_b4_k(const float* A0, const float* A1, const float* A2, const float* A3,
                    const float* B0, const float* B1, const float* B2, const float* B3,
                    float* C0, float* C1, float* C2, float* C3,
                    int M, int N, int K) {
    const int z = blockIdx.z;
    const float* A = (z == 0) ? A0 : (z == 1) ? A1 : (z == 2) ? A2 : A3;
    const float* B = (z == 0) ? B0 : (z == 1) ? B1 : (z == 2) ? B2 : B3;
    float*       C = (z == 0) ? C0 : (z == 1) ? C1 : (z == 2) ? C2 : C3;
    gemm_tf32_dev<false>(A, B, C, M, N, K);
}
// batched x2, shared A (FFN wg/wu)
__global__ __launch_bounds__(256, 2)
void gemm_tf32_b2_k(const float* A, const float* B0, const float* B1,
                    float* C0, float* C1, int M, int N, int K) {
    const float* B = (blockIdx.z == 0) ? B0 : B1;
    float*       C = (blockIdx.z == 0) ? C0 : C1;
    gemm_tf32_dev<false>(A, B, C, M, N, K);
}

// ------------------------- GEMM (small FFMA): C = A * B^T, 64x64 tile -------
// Used only for the beta projection (N=16). K must be a multiple of 16.
template<bool ACC>
__global__ __launch_bounds__(256)
void gemm_abt64(const float* __restrict__ A, const float* __restrict__ B,
                float* __restrict__ C, int M, int N, int K) {
    __shared__ float As[16][64];
    __shared__ float Bs[16][64];
    const int bm = blockIdx.y * 64;
    const int bn = blockIdx.x * 64;
    const int tid = threadIdx.x;
    const int tx = tid & 15;
    const int ty = tid >> 4;
    const int lr = tid >> 2;
    const int lk = (tid & 3) * 4;
    const int gm = bm + lr;
    const int gn = bn + lr;
    const bool mok = gm < M;
    const bool nok = gn < N;
    const float* arow = A + (size_t)(mok ? gm : 0) * K + lk;
    const float* brow = B + (size_t)(nok ? gn : 0) * K + lk;
    float acc[4][4] = {};
    float4 av = make_float4(0.f, 0.f, 0.f, 0.f);
    float4 bv = make_float4(0.f, 0.f, 0.f, 0.f);
    if (mok) av = *(const float4*)(arow);
    if (nok) bv = *(const float4*)(brow);
    for (int k0 = 0; k0 < K; k0 += 16) {
        As[lk + 0][lr] = av.x; As[lk + 1][lr] = av.y;
        As[lk + 2][lr] = av.z; As[lk + 3][lr] = av.w;
        Bs[lk + 0][lr] = bv.x; Bs[lk + 1][lr] = bv.y;
        Bs[lk + 2][lr] = bv.z; Bs[lk + 3][lr] = bv.w;
        __syncthreads();
        if (k0 + 16 < K) {
            if (mok) av = *(const float4*)(arow + k0 + 16);
            if (nok) bv = *(const float4*)(brow + k0 + 16);
        }
        #pragma unroll
        for (int kk = 0; kk < 16; kk++) {
            float a[4], b[4];
            #pragma unroll
            for (int i = 0; i < 4; i++) a[i] = As[kk][ty * 4 + i];
            #pragma unroll
            for (int j = 0; j < 4; j++) b[j] = Bs[kk][tx * 4 + j];
            #pragma unroll
            for (int i = 0; i < 4; i++)
                #pragma unroll
                for (int j = 0; j < 4; j++)
                    acc[i][j] += a[i] * b[j];
        }
        __syncthreads();
    }
    #pragma unroll
    for (int i = 0; i < 4; i++) {
        int m = bm + ty * 4 + i;
        if (m >= M) continue;
        #pragma unroll
        for (int j = 0; j < 4; j++) {
            int n = bn + tx * 4 + j;
            if (n >= N) continue;
            size_t idx = (size_t)m * N + n;
            if (ACC) C[idx] += acc[i][j];
            else     C[idx]  = acc[i][j];
        }
    }
}

// ------------------------- rmsnorm ------------------------------------------
__global__ void rmsnorm_k(const float* __restrict__ x, const float* __restrict__ w,
                          float* __restrict__ y) {
    int t = blockIdx.x;
    const float* xr = x + (size_t)t * kD;
    __shared__ float red[256];
    float s = 0.f;
    for (int d = threadIdx.x; d < kD; d += 256) { float v = xr[d]; s += v * v; }
    red[threadIdx.x] = s; __syncthreads();
    for (int o = 128; o > 0; o >>= 1) {
        if (threadIdx.x < o) red[threadIdx.x] += red[threadIdx.x + o];
        __syncthreads();
    }
    float scale = rsqrtf(red[0] / kD + 1e-6f);
    for (int d = threadIdx.x; d < kD; d += 256)
        y[(size_t)t * kD + d] = xr[d] * scale * w[d];
}

__global__ void embed_norm_k(const int* __restrict__ x, const float* __restrict__ embed,
                             const float* __restrict__ w, float* __restrict__ y) {
    int t = blockIdx.x;
    const float* xr = embed + (size_t)x[t] * kD;
    __shared__ float red[256];
    float s = 0.f;
    for (int d = threadIdx.x; d < kD; d += 256) { float v = xr[d]; s += v * v; }
    red[threadIdx.x] = s; __syncthreads();
    for (int o = 128; o > 0; o >>= 1) {
        if (threadIdx.x < o) red[threadIdx.x] += red[threadIdx.x + o];
        __syncthreads();
    }
    float scale = rsqrtf(red[0] / kD + 1e-6f);
    for (int d = threadIdx.x; d < kD; d += 256)
        y[(size_t)t * kD + d] = xr[d] * scale * w[d];
}

// ------------------------- sliding-window attention -------------------------
__global__ void swa_k(const float* __restrict__ qkv, float* __restrict__ out) {
    int i = blockIdx.x, h = blockIdx.y;
    int tid = threadIdx.x;
    __shared__ float qv[64];
    __shared__ float sp[256];
    __shared__ float red[256];
    if (tid < 64) qv[tid] = qkv[(size_t)i * 3072 + h * 64 + tid];
    __syncthreads();
    int j = i - 255 + tid;
    float s;
    if (j >= 0) {
        const float* kr = qkv + (size_t)j * 3072 + 1024 + h * 64;
        float d = 0.f;
        #pragma unroll
        for (int c = 0; c < 64; c++) d += qv[c] * kr[c];
        s = d * 0.125f;
    } else {
        s = -INFINITY;
    }
    red[tid] = s; __syncthreads();
    for (int o = 128; o > 0; o >>= 1) {
        if (tid < o) red[tid] = fmaxf(red[tid], red[tid + o]);
        __syncthreads();
    }
    float m = red[0]; __syncthreads();
    float p = expf(s - m);
    sp[tid] = p;
    red[tid] = p; __syncthreads();
    for (int o = 128; o > 0; o >>= 1) {
        if (tid < o) red[tid] += red[tid + o];
        __syncthreads();
    }
    float inv = 1.f / red[0];
    __syncthreads();
    int dh = tid & 63, part = tid >> 6;
    float acc = 0.f;
    for (int jj = part * 64; jj < part * 64 + 64; jj++) {
        int jg = i - 255 + jj;
        int jc = jg < 0 ? 0 : jg;
        acc += sp[jj] * qkv[(size_t)jc * 3072 + 2048 + h * 64 + dh];
    }
    red[tid] = acc; __syncthreads();
    if (tid < 64) {
        float o = (red[tid] + red[tid + 64] + red[tid + 128] + red[tid + 192]) * inv;
        out[(size_t)i * kD + h * 64 + tid] = o;
    }
}

// ------------------------- delta helpers ------------------------------------
__global__ void l2norm_k(float* __restrict__ p) {
    int t = blockIdx.x, h = blockIdx.y;
    float* r = p + (size_t)t * kD + h * 64;
    int lane = threadIdx.x;
    float v0 = r[lane], v1 = r[lane + 32];
    float s = v0 * v0 + v1 * v1;
    #pragma unroll
    for (int o = 16; o > 0; o >>= 1) s += __shfl_xor_sync(0xffffffffu, s, o);
    float n = fmaxf(sqrtf(s), 1e-12f);
    r[lane] = v0 / n; r[lane + 32] = v1 / n;
}

__global__ void sigmoid_k(float* __restrict__ p, int n) {
    int i = blockIdx.x * blockDim.x + threadIdx.x;
    if (i < n) p[i] = 1.f / (1.f + expf(-p[i]));
}

__global__ void cum_k(const float* __restrict__ beta, float* __restrict__ cum) {
    int h = threadIdx.x;
    float c = 0.f;
    for (int t = 0; t < kT; t++) {
        c += logf(1.f - beta[(size_t)t * kH + h] + 1e-8f);
        cum[(size_t)h * kT + t] = c;
    }
}

__global__ void delta_k(const float* __restrict__ kp, const float* __restrict__ vp,
                        const float* __restrict__ qp, const float* __restrict__ beta,
                        const float* __restrict__ cum, float* __restrict__ out) {
    int i = blockIdx.x, h = blockIdx.y;
    int tid = threadIdx.x;
    __shared__ float qv[64];
    __shared__ float sw[256];
    __shared__ float red[256];
    if (tid < 64) qv[tid] = qp[(size_t)i * kD + h * 64 + tid];
    __syncthreads();
    float ci = cum[(size_t)h * kT + i];
    int dh = tid & 63, part = tid >> 6;
    float acc = 0.f;
    for (int jb = (i >> 8) << 8; jb < kT; jb += 256) {
        int j = jb + tid;
        float w = 0.f;
        if (j >= i) {
            const float* kr = kp + (size_t)j * kD + h * 64;
            float d = 0.f;
            #pragma unroll
            for (int c = 0; c < 64; c++) d += qv[c] * kr[c];
            float ld = ci - cum[(size_t)h * kT + j];
            w = d * 0.125f * expf(fminf(ld, 0.f));
        }
        sw[tid] = w; __syncthreads();
        for (int jj = part * 64; jj < part * 64 + 64; jj++)
            acc += sw[jj] * vp[(size_t)(jb + jj) * kD + h * 64 + dh];
        __syncthreads();
    }
    red[tid] = acc; __syncthreads();
    if (tid < 64) {
        float b = beta[(size_t)i * kH + h];
        float o = red[tid] + red[tid + 64] + red[tid + 128] + red[tid + 192]
                + b * vp[(size_t)i * kD + h * 64 + tid];
        out[(size_t)i * kD + h * 64 + tid] = o;
    }
}

// ------------------------- elementwise (float4, bitwise-identical math) -----
__global__ void mix_k4(const float4* __restrict__ gate, const float4* __restrict__ local,
                       const float4* __restrict__ glob, float4* __restrict__ out, int n4) {
    int i = blockIdx.x * blockDim.x + threadIdx.x;
    if (i < n4) {
        float4 gv = gate[i], lv = local[i], bv = glob[i], ov;
        float g;
        g = 1.f / (1.f + expf(-gv.x)); ov.x = g * lv.x + (1.f - g) * bv.x;
        g = 1.f / (1.f + expf(-gv.y)); ov.y = g * lv.y + (1.f - g) * bv.y;
        g = 1.f / (1.f + expf(-gv.z)); ov.z = g * lv.z + (1.f - g) * bv.z;
        g = 1.f / (1.f + expf(-gv.w)); ov.w = g * lv.w + (1.f - g) * bv.w;
        out[i] = ov;
    }
}

__global__ void silu_mul_k4(float4* __restrict__ g, const float4* __restrict__ u, int n4) {
    int i = blockIdx.x * blockDim.x + threadIdx.x;
    if (i < n4) {
        float4 gv = g[i], uv = u[i], ov;
        ov.x = (gv.x / (1.f + expf(-gv.x))) * uv.x;
        ov.y = (gv.y / (1.f + expf(-gv.y))) * uv.y;
        ov.z = (gv.z / (1.f + expf(-gv.z))) * uv.z;
        ov.w = (gv.w / (1.f + expf(-gv.w))) * uv.w;
        g[i] = ov;
    }
}

// ------------------------- host orchestration -------------------------------
static inline float* sym(const void* symbol) {
    void* p = nullptr;
    cudaGetSymbolAddress(&p, symbol);
    return (float*)p;
}

extern "C" void kernel_launch(void* const* d_in, const int* in_sizes, int n_in,
                              void* d_out, int out_size) {
    const int*   x        = (const int*)  d_in[0];
    const float* embed    = (const float*)d_in[1];
    const float* ln_in_w  = (const float*)d_in[2];
    const float* ln1_w    = (const float*)d_in[3];
    const float* lnd_w    = (const float*)d_in[4];
    const float* qkv_w    = (const float*)d_in[5];
    const float* swa_out_w= (const float*)d_in[6];
    const float* k_w      = (const float*)d_in[7];
    const float* v_w      = (const float*)d_in[8];
    const float* q_w      = (const float*)d_in[9];
    const float* beta_w   = (const float*)d_in[10];
    const float* mem_out_w= (const float*)d_in[11];
    const float* gate_w   = (const float*)d_in[12];
    const float* comb_w   = (const float*)d_in[13];
    const float* ln2_w    = (const float*)d_in[14];
    const float* wg       = (const float*)d_in[15];
    const float* wu       = (const float*)d_in[16];
    const float* wo       = (const float*)d_in[17];
    const float* ln_out_w = (const float*)d_in[18];
    float* logits = (float*)d_out;

    float* h     = sym(g_h);
    float* h1    = sym(g_h1);
    float* h2    = sym(g_h2);
    float* hn    = sym(g_hn);
    float* qkv   = sym(g_qkv);
    float* attn  = sym(g_attn);
    float* local = sym(g_local);
    float* kp    = sym(g_kp);
    float* vp    = sym(g_vp);
    float* qp    = sym(g_qp);
    float* beta  = sym(g_beta);
    float* cum   = sym(g_cum);
    float* dout  = sym(g_dout);
    float* glob  = sym(g_glob);
    float* gate  = sym(g_gate);
    float* mixin = sym(g_mixin);
    float* ffg   = sym(g_ffg);
    float* ffu   = sym(g_ffu);

    // h = rms_norm(embed[x], ln_in_w)
    embed_norm_k<<<kT, 256>>>(x, embed, ln_in_w, h);

    for (int l = 0; l < kL; l++) {
        const float* qkv_wl  = qkv_w    + (size_t)l * 3 * kD * kD;
        const float* swo_wl  = swa_out_w+ (size_t)l * kD * kD;
        const float* k_wl    = k_w      + (size_t)l * kD * kD;
        const float* v_wl    = v_w      + (size_t)l * kD * kD;
        const float* q_wl    = q_w      + (size_t)l * kD * kD;
        const float* beta_wl = beta_w   + (size_t)l * kH * kD;
        const float* mo_wl   = mem_out_w+ (size_t)l * kD * kD;
        const float* gate_wl = gate_w   + (size_t)l * kD * kD;
        const float* comb_wl = comb_w   + (size_t)l * kD * kD;
        const float* wg_l    = wg       + (size_t)l * kFF * kD;
        const float* wu_l    = wu       + (size_t)l * kFF * kD;
        const float* wo_l    = wo       + (size_t)l * kD * kFF;

        rmsnorm_k<<<kT, 256>>>(h, ln1_w + (size_t)l * kD, h1);
        rmsnorm_k<<<kT, 256>>>(h, lnd_w + (size_t)l * kD, h2);

        // local branch
        gemm_tf32_k<<<dim3(3 * kD / 128, kT / 128), 256>>>(h1, qkv_wl, qkv, kT, 3 * kD, kD);
        swa_k<<<dim3(kT, kH), 256>>>(qkv, attn);
        gemm_tf32_k<<<dim3(kD / 128, kT / 128), 256>>>(attn, swo_wl, local, kT, kD, kD);

        // batched: gate (h1) + k/v/q projections (h2)
        gemm_tf32_b4_k<<<dim3(kD / 128, kT / 128, 4), 256>>>(
            h1, h2, h2, h2, gate_wl, k_wl, v_wl, q_wl,
            gate, kp, vp, qp, kT, kD, kD);
        gemm_abt64<false><<<dim3(1, kT / 64), 256>>>(h2, beta_wl, beta, kT, kH, kD);
        sigmoid_k<<<(kT * kH + 255) / 256, 256>>>(beta, kT * kH);
        l2norm_k<<<dim3(kT, kH), 32>>>(kp);
        l2norm_k<<<dim3(kT, kH), 32>>>(qp);
        cum_k<<<1, kH>>>(beta, cum);
        delta_k<<<dim3(kT, kH), 256>>>(kp, vp, qp, beta, cum, dout);
        gemm_tf32_k<<<dim3(kD / 128, kT / 128), 256>>>(dout, mo_wl, glob, kT, kD, kD);

        // gate mix + combine, residual
        mix_k4<<<(kT * kD / 4 + 255) / 256, 256>>>(
            (const float4*)gate, (const float4*)local, (const float4*)glob,
            (float4*)mixin, kT * kD / 4);
        gemm_tf32_acc_k<<<dim3(kD / 128, kT / 128), 256>>>(mixin, comb_wl, h, kT, kD, kD);

        // FFN, residual
        rmsnorm_k<<<kT, 256>>>(h, ln2_w + (size_t)l * kD, hn);
        gemm_tf32_b2_k<<<dim3(kFF / 128, kT / 128, 2), 256>>>(hn, wg_l, wu_l, ffg, ffu, kT, kFF, kD);
        silu_mul_k4<<<(kT * kFF / 4 + 255) / 256, 256>>>(
            (float4*)ffg, (const float4*)ffu, kT * kFF / 4);
        gemm_tf32_acc_k<<<dim3(kD / 128, kT / 128), 256>>>(ffg, wo_l, h, kT, kD, kFF);
    }

    // logits = rms_norm(h, ln_out_w) @ embed^T
    rmsnorm_k<<<kT, 256>>>(h, ln_out_w, hn);
    gemm_tf32_k<<<dim3(kV / 128, kT / 128), 256>>>(hn, embed, logits, kT, kV, kD);
}